// round 1
// baseline (speedup 1.0000x reference)
#include <cuda_runtime.h>

#define NTREES 128
#define C 8
#define L 2
#define M 256
#define G 4
#define DEPTH 11
#define NTH 512

// Precomputed (softmaxed) parameters. SP is folded into A.
__device__ float g_A[2][C][C][G];    // [p][c][d][g] = softmax_c(lambda_A)[c,d,p,g] * SP[p,g]
__device__ float g_Bm[C][M][G];      // softmax over m
__device__ float g_Pi[L][C][G];      // [p][c][g] = softmax_c(lambda_Pi)[c,p,g]

// ---------------- float4 helpers ----------------
static __device__ __forceinline__ float4 f4zero() { return make_float4(0.f, 0.f, 0.f, 0.f); }
static __device__ __forceinline__ float4 add4(float4 a, float4 b) {
    return make_float4(a.x + b.x, a.y + b.y, a.z + b.z, a.w + b.w);
}
static __device__ __forceinline__ float4 mul4(float4 a, float4 b) {
    return make_float4(a.x * b.x, a.y * b.y, a.z * b.z, a.w * b.w);
}
static __device__ __forceinline__ float4 fma4(float4 a, float4 b, float4 c) {
    return make_float4(fmaf(a.x, b.x, c.x), fmaf(a.y, b.y, c.y),
                       fmaf(a.z, b.z, c.z), fmaf(a.w, b.w, c.w));
}
static __device__ __forceinline__ float4 rcp4(float4 a) {
    return make_float4(__fdividef(1.f, a.x), __fdividef(1.f, a.y),
                       __fdividef(1.f, a.z), __fdividef(1.f, a.w));
}
static __device__ __forceinline__ float4 log4(float4 a) {
    return make_float4(__logf(a.x), __logf(a.y), __logf(a.z), __logf(a.w));
}

// ---------------- precompute softmaxes ----------------
__global__ void htmm_precompute(const float* __restrict__ lA, const float* __restrict__ lB,
                                const float* __restrict__ lPi, const float* __restrict__ lSP) {
    int tid = threadIdx.x;
    if (tid < 32) {
        // Bm: softmax over m for (c,g)
        int c = tid >> 2, g = tid & 3;
        float mx = -1e30f;
        for (int m = 0; m < M; m++) mx = fmaxf(mx, lB[(c * M + m) * G + g]);
        float s = 0.f;
        for (int m = 0; m < M; m++) s += __expf(lB[(c * M + m) * G + g] - mx);
        float r = 1.f / s;
        for (int m = 0; m < M; m++) g_Bm[c][m][g] = __expf(lB[(c * M + m) * G + g] - mx) * r;
    } else if (tid < 96) {
        // A: softmax over c for each (d,p,g); fold SP[p,g]
        int t = tid - 32;
        int d = t >> 3, p = (t >> 2) & 1, g = t & 3;
        float s0 = lSP[0 * G + g], s1 = lSP[1 * G + g];
        float mxs = fmaxf(s0, s1);
        float e0 = __expf(s0 - mxs), e1 = __expf(s1 - mxs);
        float sp = (p == 0 ? e0 : e1) / (e0 + e1);
        float mx = -1e30f;
        for (int c = 0; c < C; c++) mx = fmaxf(mx, lA[((c * C + d) * L + p) * G + g]);
        float s = 0.f;
        for (int c = 0; c < C; c++) s += __expf(lA[((c * C + d) * L + p) * G + g] - mx);
        float r = sp / s;
        for (int c = 0; c < C; c++)
            g_A[p][c][d][g] = __expf(lA[((c * C + d) * L + p) * G + g] - mx) * r;
    } else if (tid < 104) {
        // Pi: softmax over c for each (p,g)
        int t = tid - 96;
        int p = t >> 2, g = t & 3;
        float mx = -1e30f;
        for (int c = 0; c < C; c++) mx = fmaxf(mx, lPi[(c * L + p) * G + g]);
        float s = 0.f;
        for (int c = 0; c < C; c++) s += __expf(lPi[(c * L + p) * G + g] - mx);
        float r = 1.f / s;
        for (int c = 0; c < C; c++) g_Pi[p][c][g] = __expf(lPi[(c * L + p) * G + g] - mx) * r;
    }
}

// ---------------- main kernel: one CTA per tree ----------------
// smem layout (float4 units):
//   betaA  [0,      8192)  : 8 planes x 1024 nodes  (levels 10,8,6,4,2,0)
//   betaB  [8192,  12288)  : 8 planes x 512 nodes   (levels 9,7,5,3,1)
//   A_s    [12288, 12416)  : [p][c][d] float4 over g
//   Bm_s   [12416, 14464)  : [c][m]    float4 over g
//   Pi_s   [14464, 14480)  : [p][c]    float4 over g
//   red    [14480, 14481)  : 4 floats
#define SMEM_F4 14481
#define SMEM_BYTES (SMEM_F4 * 16)

__global__ __launch_bounds__(NTH) void htmm_main(const int* __restrict__ pos,
                                                 const int* __restrict__ x,
                                                 float* __restrict__ out) {
    extern __shared__ float4 sm[];
    float4* betaA = sm;
    float4* betaB = sm + 8192;
    float4* A_s   = sm + 12288;
    float4* Bm_s  = sm + 12416;
    float4* Pi_s  = sm + 14464;
    float*  red   = (float*)(sm + 14480);

    const int t = blockIdx.x, tid = threadIdx.x;

    // stage constants into smem
    if (tid < 128) A_s[tid] = ((const float4*)g_A)[tid];
    for (int i = tid; i < 2048; i += NTH) Bm_s[i] = ((const float4*)g_Bm)[i];
    if (tid < 16) Pi_s[tid] = ((const float4*)g_Pi)[tid];
    if (tid < 4) red[tid] = 0.f;
    __syncthreads();

    float4 ll = f4zero();

    // ---- step l=11: leaves computed in registers, produce level-10 betas ----
    {
        const int offL = 128 * ((1 << 11) - 1) + (t << 11);
        const int offP = 128 * ((1 << 10) - 1) + (t << 10);
        for (int pa = tid; pa < 1024; pa += NTH) {
            float4 acc[8];
#pragma unroll
            for (int c = 0; c < 8; c++) acc[c] = f4zero();
#pragma unroll
            for (int s = 0; s < 2; s++) {
                int leaf = 2 * pa + s;
                int p = pos[offL + leaf];
                int m = x[offL + leaf];
                float4 b[8];
                float4 nu = f4zero();
#pragma unroll
                for (int c = 0; c < 8; c++) {
                    b[c] = mul4(Pi_s[p * 8 + c], Bm_s[c * 256 + m]);
                    nu = add4(nu, b[c]);
                }
                float4 r = rcp4(nu);
                ll = add4(ll, log4(nu));
#pragma unroll
                for (int c = 0; c < 8; c++) b[c] = mul4(b[c], r);
                const float4* Ap = A_s + p * 64;
#pragma unroll
                for (int c = 0; c < 8; c++) {
                    float4 mm = f4zero();
#pragma unroll
                    for (int d = 0; d < 8; d++) mm = fma4(Ap[c * 8 + d], b[d], mm);
                    acc[c] = add4(acc[c], mm);
                }
            }
            int m = x[offP + pa];
            float4 nu = f4zero();
#pragma unroll
            for (int c = 0; c < 8; c++) {
                acc[c] = mul4(acc[c], Bm_s[c * 256 + m]);
                nu = add4(nu, acc[c]);
            }
            float4 r = rcp4(nu);
            ll = add4(ll, log4(nu));
#pragma unroll
            for (int c = 0; c < 8; c++) betaA[c * 1024 + pa] = mul4(acc[c], r);
        }
    }
    __syncthreads();

    // ---- steps l=10..1: ping-pong betaA(even levels) / betaB(odd levels) ----
#pragma unroll 1
    for (int l = 10; l >= 1; --l) {
        const int n_ch = 1 << l;
        float4* chb = (l & 1) ? betaB : betaA;
        const int cs = (l & 1) ? 512 : 1024;
        float4* pb = (l & 1) ? betaA : betaB;
        const int ps = (l & 1) ? 1024 : 512;
        const int offC = 128 * ((1 << l) - 1) + (t << l);

        // child transform, in place (each thread touches only its own slots)
        for (int ch = tid; ch < n_ch; ch += NTH) {
            int p = pos[offC + ch];
            float4 b[8];
#pragma unroll
            for (int c = 0; c < 8; c++) b[c] = chb[c * cs + ch];
            const float4* Ap = A_s + p * 64;
#pragma unroll
            for (int c = 0; c < 8; c++) {
                float4 mm = f4zero();
#pragma unroll
                for (int d = 0; d < 8; d++) mm = fma4(Ap[c * 8 + d], b[d], mm);
                chb[c * cs + ch] = mm;
            }
        }
        __syncthreads();

        const int n_pa = n_ch >> 1;
        const int offP = 128 * ((1 << (l - 1)) - 1) + (t << (l - 1));
        for (int pa = tid; pa < n_pa; pa += NTH) {
            int m = x[offP + pa];
            float4 nu = f4zero();
            float4 v[8];
#pragma unroll
            for (int c = 0; c < 8; c++) {
                v[c] = add4(chb[c * cs + 2 * pa], chb[c * cs + 2 * pa + 1]);
                v[c] = mul4(v[c], Bm_s[c * 256 + m]);
                nu = add4(nu, v[c]);
            }
            float4 r = rcp4(nu);
            ll = add4(ll, log4(nu));
#pragma unroll
            for (int c = 0; c < 8; c++) pb[c * ps + pa] = mul4(v[c], r);
        }
        __syncthreads();
    }

    // ---- block reduction of per-thread ll (float4 over g) ----
#pragma unroll
    for (int o = 16; o; o >>= 1) {
        ll.x += __shfl_xor_sync(0xffffffffu, ll.x, o);
        ll.y += __shfl_xor_sync(0xffffffffu, ll.y, o);
        ll.z += __shfl_xor_sync(0xffffffffu, ll.z, o);
        ll.w += __shfl_xor_sync(0xffffffffu, ll.w, o);
    }
    if ((tid & 31) == 0) {
        atomicAdd(&red[0], ll.x);
        atomicAdd(&red[1], ll.y);
        atomicAdd(&red[2], ll.z);
        atomicAdd(&red[3], ll.w);
    }
    __syncthreads();
    if (tid < 4) out[t * 4 + tid] = red[tid];
}

extern "C" void kernel_launch(void* const* d_in, const int* in_sizes, int n_in,
                              void* d_out, int out_size) {
    const float* lA  = (const float*)d_in[0];
    const float* lB  = (const float*)d_in[1];
    const float* lPi = (const float*)d_in[2];
    const float* lSP = (const float*)d_in[3];
    const int*   pos = (const int*)d_in[4];
    const int*   x   = (const int*)d_in[5];
    float*       out = (float*)d_out;

    cudaFuncSetAttribute(htmm_main, cudaFuncAttributeMaxDynamicSharedMemorySize, SMEM_BYTES);

    htmm_precompute<<<1, 128>>>(lA, lB, lPi, lSP);
    htmm_main<<<NTREES, NTH, SMEM_BYTES>>>(pos, x, out);
}

// round 2
// speedup vs baseline: 1.6843x; 1.6843x over previous
#include <cuda_runtime.h>

#define NTREES 128
#define C 8
#define L 2
#define M 256
#define G 4
#define NTH 512

// Precomputed (softmaxed) parameters. SP is folded into A.
// A layout: [c][d][p][g]  -> p interleaved so p=0/1 are adjacent float4 (no bank conflict)
__device__ float g_A[C][C][L][G];
__device__ float g_Bm[C][M][G];      // softmax over m
__device__ float g_Pi[L][C][G];      // [p][c][g]

// ---------------- float4 helpers ----------------
static __device__ __forceinline__ float4 f4zero() { return make_float4(0.f, 0.f, 0.f, 0.f); }
static __device__ __forceinline__ float4 add4(float4 a, float4 b) {
    return make_float4(a.x + b.x, a.y + b.y, a.z + b.z, a.w + b.w);
}
static __device__ __forceinline__ float4 mul4(float4 a, float4 b) {
    return make_float4(a.x * b.x, a.y * b.y, a.z * b.z, a.w * b.w);
}
static __device__ __forceinline__ float4 fma4(float4 a, float4 b, float4 c) {
    return make_float4(fmaf(a.x, b.x, c.x), fmaf(a.y, b.y, c.y),
                       fmaf(a.z, b.z, c.z), fmaf(a.w, b.w, c.w));
}
static __device__ __forceinline__ float4 muls4(float4 a, float s) {
    return make_float4(a.x * s, a.y * s, a.z * s, a.w * s);
}
static __device__ __forceinline__ float4 rcp4(float4 a) {
    return make_float4(__fdividef(1.f, a.x), __fdividef(1.f, a.y),
                       __fdividef(1.f, a.z), __fdividef(1.f, a.w));
}
static __device__ __forceinline__ float4 log4(float4 a) {
    return make_float4(__logf(a.x), __logf(a.y), __logf(a.z), __logf(a.w));
}

// ---------------- precompute softmaxes (parallel) ----------------
__global__ void htmm_precompute(const float* __restrict__ lA, const float* __restrict__ lB,
                                const float* __restrict__ lPi, const float* __restrict__ lSP) {
    const int tid = threadIdx.x;
    const int wid = tid >> 5, lane = tid & 31;

    // Bm: one warp per (c,g); lane handles 8 m's. 32 warps = 1024 threads.
    {
        int c = wid >> 2, g = wid & 3;
        float v[8];
        float mx = -1e30f;
#pragma unroll
        for (int j = 0; j < 8; j++) {
            int m = lane + 32 * j;
            v[j] = lB[(c * M + m) * G + g];
            mx = fmaxf(mx, v[j]);
        }
#pragma unroll
        for (int o = 16; o; o >>= 1) mx = fmaxf(mx, __shfl_xor_sync(0xffffffffu, mx, o));
        float s = 0.f;
#pragma unroll
        for (int j = 0; j < 8; j++) { v[j] = __expf(v[j] - mx); s += v[j]; }
#pragma unroll
        for (int o = 16; o; o >>= 1) s += __shfl_xor_sync(0xffffffffu, s, o);
        float r = 1.f / s;
#pragma unroll
        for (int j = 0; j < 8; j++) g_Bm[c][lane + 32 * j][g] = v[j] * r;
    }

    // A: softmax over c per (d,p,g), fold SP[p,g]. 64 threads.
    if (tid < 64) {
        int d = tid >> 3, p = (tid >> 2) & 1, g = tid & 3;
        float s0 = lSP[0 * G + g], s1 = lSP[1 * G + g];
        float mxs = fmaxf(s0, s1);
        float e0 = __expf(s0 - mxs), e1 = __expf(s1 - mxs);
        float sp = (p == 0 ? e0 : e1) / (e0 + e1);
        float mx = -1e30f;
#pragma unroll
        for (int c = 0; c < C; c++) mx = fmaxf(mx, lA[((c * C + d) * L + p) * G + g]);
        float s = 0.f;
#pragma unroll
        for (int c = 0; c < C; c++) s += __expf(lA[((c * C + d) * L + p) * G + g] - mx);
        float r = sp / s;
#pragma unroll
        for (int c = 0; c < C; c++)
            g_A[c][d][p][g] = __expf(lA[((c * C + d) * L + p) * G + g] - mx) * r;
    } else if (tid < 72) {
        int t = tid - 64;
        int p = t >> 2, g = t & 3;
        float mx = -1e30f;
#pragma unroll
        for (int c = 0; c < C; c++) mx = fmaxf(mx, lPi[(c * L + p) * G + g]);
        float s = 0.f;
#pragma unroll
        for (int c = 0; c < C; c++) s += __expf(lPi[(c * L + p) * G + g] - mx);
        float r = 1.f / s;
#pragma unroll
        for (int c = 0; c < C; c++) g_Pi[p][c][g] = __expf(lPi[(c * L + p) * G + g] - mx) * r;
    }
}

// ---------------- main kernel: one CTA per tree ----------------
// smem (float4 units):
//   bufA [0, 4096)       : 8 planes x 512 nodes (odd levels 9,7,5,3,1)
//   bufB [4096, 6144)    : 8 planes x 256 nodes (even levels 8,6,4,2)
//   A_s  [6144, 6272)    : [c][d][p] float4 over g   (p interleaved)
//   Bm_s [6272, 8320)    : [c][m] float4 over g
//   Pi_s [8320, 8336)    : [p][c] float4 over g
//   red  [8336, 8337)    : 4 floats
#define SMEM_F4 8337
#define SMEM_BYTES (SMEM_F4 * 16)

__global__ __launch_bounds__(NTH) void htmm_main(const int* __restrict__ pos,
                                                 const int* __restrict__ x,
                                                 float* __restrict__ out) {
    extern __shared__ float4 sm[];
    float4* bufA = sm;
    float4* bufB = sm + 4096;
    float4* A_s  = sm + 6144;
    float4* Bm_s = sm + 6272;
    float4* Pi_s = sm + 8320;
    float*  red  = (float*)(sm + 8336);

    const int t = blockIdx.x, tid = threadIdx.x;

    if (tid < 128) A_s[tid] = ((const float4*)g_A)[tid];
    for (int i = tid; i < 2048; i += NTH) Bm_s[i] = ((const float4*)g_Bm)[i];
    if (tid < 16) Pi_s[tid] = ((const float4*)g_Pi)[tid];
    if (tid < 4) red[tid] = 0.f;
    __syncthreads();

    float4 ll = f4zero();

    // ---- fused levels 11 (leaves) -> 10 -> 9, all in registers; thread = one l9 node ----
    {
        const int offL  = 128 * 2047 + (t << 11);  // level 11
        const int off10 = 128 * 1023 + (t << 10);  // level 10
        const int off9  = 128 * 511  + (t << 9);   // level 9

        // 4 consecutive leaves of this thread's l9 subtree
        const int4 pL = *(const int4*)(pos + offL + 4 * tid);
        const int4 xL = *(const int4*)(x   + offL + 4 * tid);
        const int2 p10 = *(const int2*)(pos + off10 + 2 * tid);
        const int2 x10 = *(const int2*)(x   + off10 + 2 * tid);

        float4 acc9[8];
#pragma unroll
        for (int c = 0; c < 8; c++) acc9[c] = f4zero();

#pragma unroll
        for (int s10 = 0; s10 < 2; s10++) {
            float4 acc10[8];
#pragma unroll
            for (int c = 0; c < 8; c++) acc10[c] = f4zero();

#pragma unroll
            for (int s11 = 0; s11 < 2; s11++) {
                int li = 2 * s10 + s11;
                int p = (li == 0) ? pL.x : (li == 1) ? pL.y : (li == 2) ? pL.z : pL.w;
                int m = (li == 0) ? xL.x : (li == 1) ? xL.y : (li == 2) ? xL.z : xL.w;
                float4 b[8];
                float4 nu = f4zero();
#pragma unroll
                for (int c = 0; c < 8; c++) {
                    b[c] = mul4(Pi_s[p * 8 + c], Bm_s[c * 256 + m]);
                    nu = add4(nu, b[c]);
                }
                float4 r = rcp4(nu);
                ll = add4(ll, log4(nu));
#pragma unroll
                for (int c = 0; c < 8; c++) b[c] = mul4(b[c], r);
                const float4* Ap = A_s + p;
#pragma unroll
                for (int c = 0; c < 8; c++) {
                    float4 mm = f4zero();
#pragma unroll
                    for (int d = 0; d < 8; d++) mm = fma4(Ap[(c * 8 + d) * 2], b[d], mm);
                    acc10[c] = add4(acc10[c], mm);
                }
            }
            // level-10 node: emit, normalize, transform, accumulate into acc9
            int m = (s10 == 0) ? x10.x : x10.y;
            int p = (s10 == 0) ? p10.x : p10.y;
            float4 nu = f4zero();
#pragma unroll
            for (int c = 0; c < 8; c++) {
                acc10[c] = mul4(acc10[c], Bm_s[c * 256 + m]);
                nu = add4(nu, acc10[c]);
            }
            float4 r = rcp4(nu);
            ll = add4(ll, log4(nu));
#pragma unroll
            for (int c = 0; c < 8; c++) acc10[c] = mul4(acc10[c], r);
            const float4* Ap = A_s + p;
#pragma unroll
            for (int c = 0; c < 8; c++) {
                float4 mm = f4zero();
#pragma unroll
                for (int d = 0; d < 8; d++) mm = fma4(Ap[(c * 8 + d) * 2], acc10[d], mm);
                acc9[c] = add4(acc9[c], mm);
            }
        }
        // level-9 node: emit, normalize, store
        int m = x[off9 + tid];
        float4 nu = f4zero();
#pragma unroll
        for (int c = 0; c < 8; c++) {
            acc9[c] = mul4(acc9[c], Bm_s[c * 256 + m]);
            nu = add4(nu, acc9[c]);
        }
        float4 r = rcp4(nu);
        ll = add4(ll, log4(nu));
#pragma unroll
        for (int c = 0; c < 8; c++) bufA[c * 512 + tid] = mul4(acc9[c], r);
    }
    __syncthreads();

    // ---- levels 9..1: block mode for big levels, warp-0 mode for n_ch<=32 ----
#pragma unroll 1
    for (int l = 9; l >= 1; --l) {
        const int n_ch = 1 << l;
        float4* chb = (l & 1) ? bufA : bufB;
        const int cs = (l & 1) ? 512 : 256;
        float4* pb  = (l & 1) ? bufB : bufA;
        const int ps = (l & 1) ? 256 : 512;
        const int offC = 128 * ((1 << l) - 1) + (t << l);
        const int offP = 128 * ((1 << (l - 1)) - 1) + (t << (l - 1));
        const int n_pa = n_ch >> 1;

        if (l >= 6) {
            for (int ch = tid; ch < n_ch; ch += NTH) {
                int p = pos[offC + ch];
                float4 b[8];
#pragma unroll
                for (int c = 0; c < 8; c++) b[c] = chb[c * cs + ch];
                const float4* Ap = A_s + p;
#pragma unroll
                for (int c = 0; c < 8; c++) {
                    float4 mm = f4zero();
#pragma unroll
                    for (int d = 0; d < 8; d++) mm = fma4(Ap[(c * 8 + d) * 2], b[d], mm);
                    chb[c * cs + ch] = mm;
                }
            }
            __syncthreads();
            for (int pa = tid; pa < n_pa; pa += NTH) {
                int m = x[offP + pa];
                float4 nu = f4zero();
                float4 v[8];
#pragma unroll
                for (int c = 0; c < 8; c++) {
                    v[c] = add4(chb[c * cs + 2 * pa], chb[c * cs + 2 * pa + 1]);
                    v[c] = mul4(v[c], Bm_s[c * 256 + m]);
                    nu = add4(nu, v[c]);
                }
                float4 r = rcp4(nu);
                ll = add4(ll, log4(nu));
#pragma unroll
                for (int c = 0; c < 8; c++) pb[c * ps + pa] = mul4(v[c], r);
            }
            __syncthreads();
        } else if (tid < 32) {
            if (tid < n_ch) {
                int p = pos[offC + tid];
                float4 b[8];
#pragma unroll
                for (int c = 0; c < 8; c++) b[c] = chb[c * cs + tid];
                const float4* Ap = A_s + p;
#pragma unroll
                for (int c = 0; c < 8; c++) {
                    float4 mm = f4zero();
#pragma unroll
                    for (int d = 0; d < 8; d++) mm = fma4(Ap[(c * 8 + d) * 2], b[d], mm);
                    chb[c * cs + tid] = mm;
                }
            }
            __syncwarp();
            if (tid < n_pa) {
                int m = x[offP + tid];
                float4 nu = f4zero();
                float4 v[8];
#pragma unroll
                for (int c = 0; c < 8; c++) {
                    v[c] = add4(chb[c * cs + 2 * tid], chb[c * cs + 2 * tid + 1]);
                    v[c] = mul4(v[c], Bm_s[c * 256 + m]);
                    nu = add4(nu, v[c]);
                }
                float4 r = rcp4(nu);
                ll = add4(ll, log4(nu));
#pragma unroll
                for (int c = 0; c < 8; c++) pb[c * ps + tid] = mul4(v[c], r);
            }
            __syncwarp();
        }
    }

    // ---- block reduction of per-thread ll ----
#pragma unroll
    for (int o = 16; o; o >>= 1) {
        ll.x += __shfl_xor_sync(0xffffffffu, ll.x, o);
        ll.y += __shfl_xor_sync(0xffffffffu, ll.y, o);
        ll.z += __shfl_xor_sync(0xffffffffu, ll.z, o);
        ll.w += __shfl_xor_sync(0xffffffffu, ll.w, o);
    }
    if ((tid & 31) == 0) {
        atomicAdd(&red[0], ll.x);
        atomicAdd(&red[1], ll.y);
        atomicAdd(&red[2], ll.z);
        atomicAdd(&red[3], ll.w);
    }
    __syncthreads();
    if (tid < 4) out[t * 4 + tid] = red[tid];
}

extern "C" void kernel_launch(void* const* d_in, const int* in_sizes, int n_in,
                              void* d_out, int out_size) {
    const float* lA  = (const float*)d_in[0];
    const float* lB  = (const float*)d_in[1];
    const float* lPi = (const float*)d_in[2];
    const float* lSP = (const float*)d_in[3];
    const int*   pos = (const int*)d_in[4];
    const int*   x   = (const int*)d_in[5];
    float*       out = (float*)d_out;

    cudaFuncSetAttribute(htmm_main, cudaFuncAttributeMaxDynamicSharedMemorySize, SMEM_BYTES);

    htmm_precompute<<<1, 1024>>>(lA, lB, lPi, lSP);
    htmm_main<<<NTREES, NTH, SMEM_BYTES>>>(pos, x, out);
}

// round 3
// speedup vs baseline: 1.6881x; 1.0022x over previous
#include <cuda_runtime.h>

#define NTREES 128
#define C 8
#define L 2
#define M 256
#define G 4
#define NTH 512

// Precomputed (softmaxed) parameters. SP folded into A.
// A layout: [c][d][p][g] -> p interleaved, so p=0/1 float4s are adjacent (one 32B window)
__device__ float g_A[C][C][L][G];
__device__ float g_Bm[C][M][G];
__device__ float g_Pi[L][C][G];

// ---------------- float4 helpers ----------------
static __device__ __forceinline__ float4 f4zero() { return make_float4(0.f, 0.f, 0.f, 0.f); }
static __device__ __forceinline__ float4 add4(float4 a, float4 b) {
    return make_float4(a.x + b.x, a.y + b.y, a.z + b.z, a.w + b.w);
}
static __device__ __forceinline__ float4 mul4(float4 a, float4 b) {
    return make_float4(a.x * b.x, a.y * b.y, a.z * b.z, a.w * b.w);
}
static __device__ __forceinline__ float4 fma4(float4 a, float4 b, float4 c) {
    return make_float4(fmaf(a.x, b.x, c.x), fmaf(a.y, b.y, c.y),
                       fmaf(a.z, b.z, c.z), fmaf(a.w, b.w, c.w));
}
static __device__ __forceinline__ float4 rcp4(float4 a) {
    return make_float4(__fdividef(1.f, a.x), __fdividef(1.f, a.y),
                       __fdividef(1.f, a.z), __fdividef(1.f, a.w));
}
static __device__ __forceinline__ float4 log4(float4 a) {
    return make_float4(__logf(a.x), __logf(a.y), __logf(a.z), __logf(a.w));
}

// ---------------- precompute softmaxes (parallel) ----------------
__global__ void htmm_precompute(const float* __restrict__ lA, const float* __restrict__ lB,
                                const float* __restrict__ lPi, const float* __restrict__ lSP) {
    const int tid = threadIdx.x;
    const int wid = tid >> 5, lane = tid & 31;

    // Bm: one warp per (c,g)
    {
        int c = wid >> 2, g = wid & 3;
        float v[8];
        float mx = -1e30f;
#pragma unroll
        for (int j = 0; j < 8; j++) {
            int m = lane + 32 * j;
            v[j] = lB[(c * M + m) * G + g];
            mx = fmaxf(mx, v[j]);
        }
#pragma unroll
        for (int o = 16; o; o >>= 1) mx = fmaxf(mx, __shfl_xor_sync(0xffffffffu, mx, o));
        float s = 0.f;
#pragma unroll
        for (int j = 0; j < 8; j++) { v[j] = __expf(v[j] - mx); s += v[j]; }
#pragma unroll
        for (int o = 16; o; o >>= 1) s += __shfl_xor_sync(0xffffffffu, s, o);
        float r = 1.f / s;
#pragma unroll
        for (int j = 0; j < 8; j++) g_Bm[c][lane + 32 * j][g] = v[j] * r;
    }

    if (tid < 64) {
        // A: softmax over c per (d,p,g), fold SP[p,g]
        int d = tid >> 3, p = (tid >> 2) & 1, g = tid & 3;
        float s0 = lSP[0 * G + g], s1 = lSP[1 * G + g];
        float mxs = fmaxf(s0, s1);
        float e0 = __expf(s0 - mxs), e1 = __expf(s1 - mxs);
        float sp = (p == 0 ? e0 : e1) / (e0 + e1);
        float mx = -1e30f;
#pragma unroll
        for (int c = 0; c < C; c++) mx = fmaxf(mx, lA[((c * C + d) * L + p) * G + g]);
        float s = 0.f;
#pragma unroll
        for (int c = 0; c < C; c++) s += __expf(lA[((c * C + d) * L + p) * G + g] - mx);
        float r = sp / s;
#pragma unroll
        for (int c = 0; c < C; c++)
            g_A[c][d][p][g] = __expf(lA[((c * C + d) * L + p) * G + g] - mx) * r;
    } else if (tid < 72) {
        int t2 = tid - 64;
        int p = t2 >> 2, g = t2 & 3;
        float mx = -1e30f;
#pragma unroll
        for (int c = 0; c < C; c++) mx = fmaxf(mx, lPi[(c * L + p) * G + g]);
        float s = 0.f;
#pragma unroll
        for (int c = 0; c < C; c++) s += __expf(lPi[(c * L + p) * G + g] - mx);
        float r = 1.f / s;
#pragma unroll
        for (int c = 0; c < C; c++) g_Pi[p][c][g] = __expf(lPi[(c * L + p) * G + g] - mx) * r;
    }
}

// ---------------- main kernel: one CTA per tree ----------------
// Messages (already A-transformed) ping-pong between bufA (odd levels, stride 512)
// and bufB (even levels, stride 256).
// smem (float4 units):
//   bufA [0, 4096)     : 8 planes x 512  (levels 9,7,5,3,1)
//   bufB [4096, 6144)  : 8 planes x 256  (levels 8,6,4,2)
//   A_s  [6144, 6272)  : [c][d][p] float4 over g
//   Bm_s [6272, 8320)  : [c][m] float4 over g
//   Pi_s [8320, 8336)  : [p][c] float4 over g
//   red  [8336, 8337)  : 4 floats
#define SMEM_F4 8337
#define SMEM_BYTES (SMEM_F4 * 16)

__global__ __launch_bounds__(NTH) void htmm_main(const int* __restrict__ pos,
                                                 const int* __restrict__ x,
                                                 float* __restrict__ out) {
    extern __shared__ float4 sm[];
    float4* bufA = sm;
    float4* bufB = sm + 4096;
    float4* A_s  = sm + 6144;
    float4* Bm_s = sm + 6272;
    float4* Pi_s = sm + 8320;
    float*  red  = (float*)(sm + 8336);

    const int t = blockIdx.x, tid = threadIdx.x;

    if (tid < 128) A_s[tid] = ((const float4*)g_A)[tid];
    for (int i = tid; i < 2048; i += NTH) Bm_s[i] = ((const float4*)g_Bm)[i];
    if (tid < 16) Pi_s[tid] = ((const float4*)g_Pi)[tid];
    if (tid < 4) red[tid] = 0.f;
    __syncthreads();

    float4 ll = f4zero();

    // ---- fused levels 11 -> 10 -> 9 in registers; thread = one l9 node ----
    // Produces TRANSFORMED level-9 messages in bufA.
    {
        const int offL  = 128 * 2047 + (t << 11);
        const int off10 = 128 * 1023 + (t << 10);
        const int off9  = 128 * 511  + (t << 9);

        const int4 pL  = *(const int4*)(pos + offL + 4 * tid);
        const int4 xL  = *(const int4*)(x   + offL + 4 * tid);
        const int2 p10 = *(const int2*)(pos + off10 + 2 * tid);
        const int2 x10 = *(const int2*)(x   + off10 + 2 * tid);

        float4 acc9[8];
#pragma unroll
        for (int c = 0; c < 8; c++) acc9[c] = f4zero();

#pragma unroll
        for (int s10 = 0; s10 < 2; s10++) {
            float4 acc10[8];
#pragma unroll
            for (int c = 0; c < 8; c++) acc10[c] = f4zero();

#pragma unroll
            for (int s11 = 0; s11 < 2; s11++) {
                int li = 2 * s10 + s11;
                int p = (li == 0) ? pL.x : (li == 1) ? pL.y : (li == 2) ? pL.z : pL.w;
                int m = (li == 0) ? xL.x : (li == 1) ? xL.y : (li == 2) ? xL.z : xL.w;
                float4 b[8];
                float4 nu = f4zero();
#pragma unroll
                for (int c = 0; c < 8; c++) {
                    b[c] = mul4(Pi_s[p * 8 + c], Bm_s[c * 256 + m]);
                    nu = add4(nu, b[c]);
                }
                float4 r = rcp4(nu);
                ll = add4(ll, log4(nu));
#pragma unroll
                for (int c = 0; c < 8; c++) b[c] = mul4(b[c], r);
                const float4* Ap = A_s + p;
#pragma unroll
                for (int c = 0; c < 8; c++) {
                    float4 mm = f4zero();
#pragma unroll
                    for (int d = 0; d < 8; d++) mm = fma4(Ap[(c * 8 + d) * 2], b[d], mm);
                    acc10[c] = add4(acc10[c], mm);
                }
            }
            int m = (s10 == 0) ? x10.x : x10.y;
            int p = (s10 == 0) ? p10.x : p10.y;
            float4 nu = f4zero();
#pragma unroll
            for (int c = 0; c < 8; c++) {
                acc10[c] = mul4(acc10[c], Bm_s[c * 256 + m]);
                nu = add4(nu, acc10[c]);
            }
            float4 r = rcp4(nu);
            ll = add4(ll, log4(nu));
#pragma unroll
            for (int c = 0; c < 8; c++) acc10[c] = mul4(acc10[c], r);
            const float4* Ap = A_s + p;
#pragma unroll
            for (int c = 0; c < 8; c++) {
                float4 mm = f4zero();
#pragma unroll
                for (int d = 0; d < 8; d++) mm = fma4(Ap[(c * 8 + d) * 2], acc10[d], mm);
                acc9[c] = add4(acc9[c], mm);
            }
        }
        // level-9 node: emit, normalize, TRANSFORM, store message
        int m = x[off9 + tid];
        int p9 = pos[off9 + tid];
        float4 nu = f4zero();
#pragma unroll
        for (int c = 0; c < 8; c++) {
            acc9[c] = mul4(acc9[c], Bm_s[c * 256 + m]);
            nu = add4(nu, acc9[c]);
        }
        float4 r = rcp4(nu);
        ll = add4(ll, log4(nu));
#pragma unroll
        for (int c = 0; c < 8; c++) acc9[c] = mul4(acc9[c], r);
        const float4* Ap = A_s + p9;
#pragma unroll
        for (int c = 0; c < 8; c++) {
            float4 mm = f4zero();
#pragma unroll
            for (int d = 0; d < 8; d++) mm = fma4(Ap[(c * 8 + d) * 2], acc9[d], mm);
            bufA[c * 512 + tid] = mm;
        }
    }
    __syncthreads();

    // ---- single-phase levels: l = child level, produce parents at l-1 ----
#pragma unroll 1
    for (int l = 9; l >= 7; --l) {
        const int n_pa = 1 << (l - 1);            // 256, 128, 64
        float4* chb = (l & 1) ? bufA : bufB;
        const int cs = (l & 1) ? 512 : 256;
        float4* pb  = (l & 1) ? bufB : bufA;
        const int ps = (l & 1) ? 256 : 512;
        const int offP = 128 * ((1 << (l - 1)) - 1) + (t << (l - 1));

        if (tid < n_pa) {
            const int pa = tid;
            int m = x[offP + pa];
            int p = pos[offP + pa];
            float4 v[8];
            float4 nu = f4zero();
#pragma unroll
            for (int c = 0; c < 8; c++) {
                v[c] = add4(chb[c * cs + 2 * pa], chb[c * cs + 2 * pa + 1]);
                v[c] = mul4(v[c], Bm_s[c * 256 + m]);
                nu = add4(nu, v[c]);
            }
            float4 r = rcp4(nu);
            ll = add4(ll, log4(nu));
#pragma unroll
            for (int c = 0; c < 8; c++) v[c] = mul4(v[c], r);
            const float4* Ap = A_s + p;
#pragma unroll
            for (int c = 0; c < 8; c++) {
                float4 mm = f4zero();
#pragma unroll
                for (int d = 0; d < 8; d++) mm = fma4(Ap[(c * 8 + d) * 2], v[d], mm);
                pb[c * ps + pa] = mm;
            }
        }
        __syncthreads();
    }

    // ---- warp-0 tail: l = 6..1 (n_pa = 32..1) ----
    if (tid < 32) {
#pragma unroll 1
        for (int l = 6; l >= 1; --l) {
            const int n_pa = 1 << (l - 1);
            float4* chb = (l & 1) ? bufA : bufB;
            const int cs = (l & 1) ? 512 : 256;
            float4* pb  = (l & 1) ? bufB : bufA;
            const int ps = (l & 1) ? 256 : 512;
            const int offP = 128 * ((1 << (l - 1)) - 1) + (t << (l - 1));

            if (tid < n_pa) {
                const int pa = tid;
                int m = x[offP + pa];
                float4 v[8];
                float4 nu = f4zero();
#pragma unroll
                for (int c = 0; c < 8; c++) {
                    v[c] = add4(chb[c * cs + 2 * pa], chb[c * cs + 2 * pa + 1]);
                    v[c] = mul4(v[c], Bm_s[c * 256 + m]);
                    nu = add4(nu, v[c]);
                }
                ll = add4(ll, log4(nu));
                if (l > 1) {
                    int p = pos[offP + pa];
                    float4 r = rcp4(nu);
#pragma unroll
                    for (int c = 0; c < 8; c++) v[c] = mul4(v[c], r);
                    const float4* Ap = A_s + p;
#pragma unroll
                    for (int c = 0; c < 8; c++) {
                        float4 mm = f4zero();
#pragma unroll
                        for (int d = 0; d < 8; d++) mm = fma4(Ap[(c * 8 + d) * 2], v[d], mm);
                        pb[c * ps + pa] = mm;
                    }
                }
            }
            __syncwarp();
        }
    }

    // ---- block reduction of per-thread ll ----
#pragma unroll
    for (int o = 16; o; o >>= 1) {
        ll.x += __shfl_xor_sync(0xffffffffu, ll.x, o);
        ll.y += __shfl_xor_sync(0xffffffffu, ll.y, o);
        ll.z += __shfl_xor_sync(0xffffffffu, ll.z, o);
        ll.w += __shfl_xor_sync(0xffffffffu, ll.w, o);
    }
    if ((tid & 31) == 0) {
        atomicAdd(&red[0], ll.x);
        atomicAdd(&red[1], ll.y);
        atomicAdd(&red[2], ll.z);
        atomicAdd(&red[3], ll.w);
    }
    __syncthreads();
    if (tid < 4) out[t * 4 + tid] = red[tid];
}

extern "C" void kernel_launch(void* const* d_in, const int* in_sizes, int n_in,
                              void* d_out, int out_size) {
    const float* lA  = (const float*)d_in[0];
    const float* lB  = (const float*)d_in[1];
    const float* lPi = (const float*)d_in[2];
    const float* lSP = (const float*)d_in[3];
    const int*   pos = (const int*)d_in[4];
    const int*   x   = (const int*)d_in[5];
    float*       out = (float*)d_out;

    cudaFuncSetAttribute(htmm_main, cudaFuncAttributeMaxDynamicSharedMemorySize, SMEM_BYTES);

    htmm_precompute<<<1, 1024>>>(lA, lB, lPi, lSP);
    htmm_main<<<NTREES, NTH, SMEM_BYTES>>>(pos, x, out);
}